// round 1
// baseline (speedup 1.0000x reference)
#include <cuda_runtime.h>

// Scratch for the precontracted weight matrix T[o][i] (O*8 floats, O<=1024).
__device__ float g_T[8192];

// Sign of e_a * e_b reordering for Cl(3,0) (all metric signs +1):
// (-1)^{#pairs (p in a, q in b, p > q)}
__device__ __forceinline__ float blade_sign(int a, int b) {
    int swaps = 0;
    int t = a >> 1;
    while (t) { swaps += __popc(t & b); t >>= 1; }
    return (swaps & 1) ? -1.0f : 1.0f;
}

// T[o,i] = sum_{h,j} W_in[h,j] * S[i,j] * sigma[i^j] * W_out[o,h,i^j]
// One block per o, reduce over h across 128 threads.
__global__ void compute_T_kernel(const float* __restrict__ W_in,
                                 const float* __restrict__ W_out,
                                 int H)
{
    const int o = blockIdx.x;
    const int tid = threadIdx.x;

    // c[i][j] = S[i][j] * sigma[i^j]; all-constant after unroll (folds at compile time)
    float sigma[8];
    #pragma unroll
    for (int k = 0; k < 8; k++) sigma[k] = blade_sign(k, k);
    float c[8][8];
    #pragma unroll
    for (int i = 0; i < 8; i++)
        #pragma unroll
        for (int j = 0; j < 8; j++)
            c[i][j] = blade_sign(i, j) * sigma[i ^ j];

    float acc[8];
    #pragma unroll
    for (int i = 0; i < 8; i++) acc[i] = 0.0f;

    const float* woutBase = W_out + (size_t)o * H * 8;
    for (int h = tid; h < H; h += blockDim.x) {
        float4 a0 = *(const float4*)(W_in + h * 8);
        float4 a1 = *(const float4*)(W_in + h * 8 + 4);
        float4 b0 = *(const float4*)(woutBase + h * 8);
        float4 b1 = *(const float4*)(woutBase + h * 8 + 4);
        float win[8]  = {a0.x, a0.y, a0.z, a0.w, a1.x, a1.y, a1.z, a1.w};
        float wout[8] = {b0.x, b0.y, b0.z, b0.w, b1.x, b1.y, b1.z, b1.w};
        #pragma unroll
        for (int i = 0; i < 8; i++) {
            float s = 0.0f;
            #pragma unroll
            for (int j = 0; j < 8; j++)
                s += c[i][j] * win[j] * wout[i ^ j];
            acc[i] += s;
        }
    }

    __shared__ float red[128 * 8];
    #pragma unroll
    for (int i = 0; i < 8; i++) red[tid * 8 + i] = acc[i];
    __syncthreads();
    for (int s = 64; s > 0; s >>= 1) {
        if (tid < s) {
            #pragma unroll
            for (int i = 0; i < 8; i++)
                red[tid * 8 + i] += red[(tid + s) * 8 + i];
        }
        __syncthreads();
    }
    if (tid < 8) g_T[o * 8 + tid] = red[tid];
}

// out[b,o] = alpha * sum_i x[b,i] * T[o,i]
// One block per b; T staged into shared transposed [i][o] for conflict-free reads.
__global__ void finalize_kernel(const float* __restrict__ x,
                                float* __restrict__ out,
                                int O, float alpha)
{
    extern __shared__ float Ts[];  // [8][O]
    for (int idx = threadIdx.x; idx < O * 8; idx += blockDim.x) {
        int o = idx >> 3, i = idx & 7;
        Ts[i * O + o] = g_T[idx];
    }
    __syncthreads();

    const int b = blockIdx.x;
    float4 x0 = *(const float4*)(x + b * 8);
    float4 x1 = *(const float4*)(x + b * 8 + 4);

    for (int o = threadIdx.x; o < O; o += blockDim.x) {
        float s = x0.x * Ts[o]         + x0.y * Ts[O + o]
                + x0.z * Ts[2 * O + o] + x0.w * Ts[3 * O + o]
                + x1.x * Ts[4 * O + o] + x1.y * Ts[5 * O + o]
                + x1.z * Ts[6 * O + o] + x1.w * Ts[7 * O + o];
        out[(size_t)b * O + o] = alpha * s;
    }
}

extern "C" void kernel_launch(void* const* d_in, const int* in_sizes, int n_in,
                              void* d_out, int out_size)
{
    const float* x     = (const float*)d_in[0];  // [B,8]
    const float* W_in  = (const float*)d_in[1];  // [H,1,8]
    const float* W_out = (const float*)d_in[2];  // [O,H,8]

    const int B = in_sizes[0] / 8;
    const int H = in_sizes[1] / 8;
    const int O = in_sizes[2] / (H * 8);

    // alpha = 1 - (1-dt)^n_free, dt=0.1, n_free=10
    double p = 1.0;
    for (int i = 0; i < 10; i++) p *= 0.9;
    const float alpha = (float)(1.0 - p);

    compute_T_kernel<<<O, 128>>>(W_in, W_out, H);
    finalize_kernel<<<B, 128, O * 8 * sizeof(float)>>>(x, (float*)d_out, O, alpha);
}

// round 3
// speedup vs baseline: 1.7122x; 1.7122x over previous
#include <cuda_runtime.h>

// Precontracted weight matrix T[o][i] (O*8 floats, O<=1024), alpha pre-folded.
__device__ float g_T[8192];

// Sign of e_a * e_b reordering for Cl(3,0) (all metric signs +1).
__device__ __forceinline__ float blade_sign(int a, int b) {
    int swaps = 0;
    int t = a >> 1;
    while (t) { swaps += __popc(t & b); t >>= 1; }
    return (swaps & 1) ? -1.0f : 1.0f;
}

// T[o,i] = alpha * sum_{h,j} W_in[h,j] * S[i,j] * sigma[i^j] * W_out[o,h,i^j]
// One block per o, 256 threads, warp-shuffle reduction.
__global__ void compute_T_kernel(const float* __restrict__ W_in,
                                 const float* __restrict__ W_out,
                                 int H, float alpha)
{
    const int o = blockIdx.x;
    const int tid = threadIdx.x;

    // c[i][j] = S[i][j] * sigma[i^j]; compile-time constants after unroll
    float sigma[8];
    #pragma unroll
    for (int k = 0; k < 8; k++) sigma[k] = blade_sign(k, k);
    float c[8][8];
    #pragma unroll
    for (int i = 0; i < 8; i++)
        #pragma unroll
        for (int j = 0; j < 8; j++)
            c[i][j] = blade_sign(i, j) * sigma[i ^ j];

    float acc[8];
    #pragma unroll
    for (int i = 0; i < 8; i++) acc[i] = 0.0f;

    const float* woutBase = W_out + (size_t)o * H * 8;
    for (int h = tid; h < H; h += blockDim.x) {
        float4 a0 = *(const float4*)(W_in + h * 8);
        float4 a1 = *(const float4*)(W_in + h * 8 + 4);
        float4 b0 = *(const float4*)(woutBase + h * 8);
        float4 b1 = *(const float4*)(woutBase + h * 8 + 4);
        float win[8]  = {a0.x, a0.y, a0.z, a0.w, a1.x, a1.y, a1.z, a1.w};
        float wout[8] = {b0.x, b0.y, b0.z, b0.w, b1.x, b1.y, b1.z, b1.w};
        #pragma unroll
        for (int i = 0; i < 8; i++) {
            float s = 0.0f;
            #pragma unroll
            for (int j = 0; j < 8; j++)
                s += c[i][j] * win[j] * wout[i ^ j];
            acc[i] += s;
        }
    }

    // warp reduction
    #pragma unroll
    for (int i = 0; i < 8; i++) {
        #pragma unroll
        for (int off = 16; off > 0; off >>= 1)
            acc[i] += __shfl_xor_sync(0xffffffff, acc[i], off);
    }

    __shared__ float red[8][8];   // [warp][i]
    const int lane = tid & 31, w = tid >> 5;
    const int nw = blockDim.x >> 5;
    if (lane == 0) {
        #pragma unroll
        for (int i = 0; i < 8; i++) red[w][i] = acc[i];
    }
    __syncthreads();
    if (tid < 8) {
        float s = 0.0f;
        for (int ww = 0; ww < nw; ww++) s += red[ww][tid];
        g_T[o * 8 + tid] = alpha * s;
    }
}

// Fast finalize for O==128: out[b, og*4+c] = sum_i x[b,i] * T[og*4+c, i]
// 16 batch rows per block, 256 threads: tid%32 = o-group, tid/32 = row slice.
#define F_ROWS 16
__global__ void finalize128_kernel(const float* __restrict__ x,
                                   float* __restrict__ out)
{
    __shared__ float Ts[32 * 33];   // 32 o-groups x 32 floats, padded stride 33
    __shared__ float xs[F_ROWS * 9];

    const int tid = threadIdx.x;
    // g_T has O*8 = 1024 valid floats; idx = o*8+i -> group og = idx>>5 (0..31),
    // within-group k = idx&31 (since (o&3)*8+i < 32).
    for (int idx = tid; idx < 1024; idx += 256)
        Ts[(idx >> 5) * 33 + (idx & 31)] = g_T[idx];

    const int b0 = blockIdx.x * F_ROWS;
    for (int idx = tid; idx < F_ROWS * 8; idx += 256)
        xs[(idx >> 3) * 9 + (idx & 7)] = x[b0 * 8 + idx];
    __syncthreads();

    const int og = tid & 31;
    const int bq = tid >> 5;   // 0..7

    float t[32];
    #pragma unroll
    for (int k = 0; k < 32; k++) t[k] = Ts[og * 33 + k];  // conflict-free (stride 33)

    #pragma unroll
    for (int r = 0; r < F_ROWS / 8; r++) {
        const int bl = bq + r * 8;
        float xv[8];
        #pragma unroll
        for (int i = 0; i < 8; i++) xv[i] = xs[bl * 9 + i];  // broadcast within warp

        float4 o4;
        float s0 = 0, s1 = 0, s2 = 0, s3 = 0;
        #pragma unroll
        for (int i = 0; i < 8; i++) {
            s0 += xv[i] * t[i];
            s1 += xv[i] * t[8 + i];
            s2 += xv[i] * t[16 + i];
            s3 += xv[i] * t[24 + i];
        }
        o4.x = s0; o4.y = s1; o4.z = s2; o4.w = s3;
        *(float4*)(out + (size_t)(b0 + bl) * 128 + og * 4) = o4;
    }
}

// Generic fallback (any O): one block per b.
__global__ void finalize_generic_kernel(const float* __restrict__ x,
                                        float* __restrict__ out, int O)
{
    extern __shared__ float Tg[];  // [8][O] transposed
    for (int idx = threadIdx.x; idx < O * 8; idx += blockDim.x) {
        int o = idx >> 3, i = idx & 7;
        Tg[i * O + o] = g_T[idx];
    }
    __syncthreads();
    const int b = blockIdx.x;
    float4 x0 = *(const float4*)(x + b * 8);
    float4 x1 = *(const float4*)(x + b * 8 + 4);
    for (int o = threadIdx.x; o < O; o += blockDim.x) {
        float s = x0.x * Tg[o]         + x0.y * Tg[O + o]
                + x0.z * Tg[2 * O + o] + x0.w * Tg[3 * O + o]
                + x1.x * Tg[4 * O + o] + x1.y * Tg[5 * O + o]
                + x1.z * Tg[6 * O + o] + x1.w * Tg[7 * O + o];
        out[(size_t)b * O + o] = s;
    }
}

extern "C" void kernel_launch(void* const* d_in, const int* in_sizes, int n_in,
                              void* d_out, int out_size)
{
    const float* x     = (const float*)d_in[0];  // [B,8]
    const float* W_in  = (const float*)d_in[1];  // [H,1,8]
    const float* W_out = (const float*)d_in[2];  // [O,H,8]

    const int B = in_sizes[0] / 8;
    const int H = in_sizes[1] / 8;
    const int O = in_sizes[2] / (H * 8);

    // alpha = 1 - (1-dt)^n_free, dt=0.1, n_free=10
    double p = 1.0;
    for (int i = 0; i < 10; i++) p *= 0.9;
    const float alpha = (float)(1.0 - p);

    compute_T_kernel<<<O, 256>>>(W_in, W_out, H, alpha);

    if (O == 128 && (B % F_ROWS) == 0) {
        finalize128_kernel<<<B / F_ROWS, 256>>>(x, (float*)d_out);
    } else {
        finalize_generic_kernel<<<B, 128, O * 8 * sizeof(float)>>>(x, (float*)d_out, O);
    }
}